// round 12
// baseline (speedup 1.0000x reference)
#include <cuda_runtime.h>
#include <cuda_bf16.h>

// DCT-II basis constants: Ak = cos(k*pi/16), F0 = 1/sqrt(8)
#define A1 0.98078528040323044f
#define A2 0.92387953251128674f
#define A3 0.83146961230254524f
#define A4 0.70710678118654752f
#define A5 0.55557023301960218f
#define A6 0.38268343236508978f
#define A7 0.19509032201612827f
#define F0 0.35355339059327373f

__global__ void __launch_bounds__(256, 2)
jpeg_dct_kernel(const float* __restrict__ img, const float* __restrict__ qf,
                float* __restrict__ out)
{
    // Orthonormal DCT-II matrix (compile-time consts -> FFMA immediates)
    const float C[8][8] = {
        { F0,      F0,      F0,      F0,      F0,      F0,      F0,      F0     },
        { .5f*A1,  .5f*A3,  .5f*A5,  .5f*A7, -.5f*A7, -.5f*A5, -.5f*A3, -.5f*A1},
        { .5f*A2,  .5f*A6, -.5f*A6, -.5f*A2, -.5f*A2, -.5f*A6,  .5f*A6,  .5f*A2},
        { .5f*A3, -.5f*A7, -.5f*A1, -.5f*A5,  .5f*A5,  .5f*A1,  .5f*A7, -.5f*A3},
        { .5f*A4, -.5f*A4, -.5f*A4,  .5f*A4,  .5f*A4, -.5f*A4, -.5f*A4,  .5f*A4},
        { .5f*A5, -.5f*A1,  .5f*A7,  .5f*A3, -.5f*A3, -.5f*A7,  .5f*A1, -.5f*A5},
        { .5f*A6, -.5f*A2,  .5f*A2, -.5f*A6, -.5f*A6,  .5f*A2, -.5f*A2,  .5f*A6},
        { .5f*A7, -.5f*A5,  .5f*A3, -.5f*A1,  .5f*A1, -.5f*A3,  .5f*A5, -.5f*A7},
    };
    const float Qt[8][8] = {
        {16,11,10,16,24,40,51,61},
        {12,12,14,19,26,58,60,55},
        {14,13,16,24,40,57,69,56},
        {14,17,22,29,51,87,80,62},
        {18,22,37,56,68,109,103,77},
        {24,36,55,64,81,104,113,92},
        {49,64,78,87,103,121,120,101},
        {72,92,95,98,112,100,103,99},
    };

    int tid = blockIdx.x * 256 + threadIdx.x;   // 262144 threads, one per 8x8 block
    int w  = tid & 127;
    int hb = (tid >> 7) & 127;
    int b  = tid >> 14;

    const float* p = img + (b << 20) + (hb << 13) + (w << 3);

    // t[k][c] accumulators; -128 pixel shift only affects the DC row (128*8*F0).
    float t[8][8];
#pragma unroll
    for (int c = 0; c < 8; ++c) t[0][c] = -362.03867196751236f;
#pragma unroll
    for (int k = 1; k < 8; ++k)
#pragma unroll
        for (int c = 0; c < 8; ++c) t[k][c] = 0.0f;

    // Pass 1: one 256-bit load per image row (8 total), row-pair symmetry.
    // Even k accumulate C[k][r]*(x[r]+x[7-r]); odd k use (x[r]-x[7-r]).
#pragma unroll
    for (int r = 0; r < 4; ++r) {
        unsigned a0,a1,a2,a3,a4,a5,a6,a7, b0,b1,b2,b3,b4,b5,b6,b7;
        asm volatile(
            "ld.global.nc.L2::evict_last.v8.b32 {%0,%1,%2,%3,%4,%5,%6,%7}, [%8];"
            : "=r"(a0),"=r"(a1),"=r"(a2),"=r"(a3),
              "=r"(a4),"=r"(a5),"=r"(a6),"=r"(a7)
            : "l"(p + (r << 10)));
        asm volatile(
            "ld.global.nc.L2::evict_last.v8.b32 {%0,%1,%2,%3,%4,%5,%6,%7}, [%8];"
            : "=r"(b0),"=r"(b1),"=r"(b2),"=r"(b3),
              "=r"(b4),"=r"(b5),"=r"(b6),"=r"(b7)
            : "l"(p + ((7 - r) << 10)));
        float a[8] = { __uint_as_float(a0), __uint_as_float(a1),
                       __uint_as_float(a2), __uint_as_float(a3),
                       __uint_as_float(a4), __uint_as_float(a5),
                       __uint_as_float(a6), __uint_as_float(a7) };
        float bb[8] = { __uint_as_float(b0), __uint_as_float(b1),
                        __uint_as_float(b2), __uint_as_float(b3),
                        __uint_as_float(b4), __uint_as_float(b5),
                        __uint_as_float(b6), __uint_as_float(b7) };
        float s[8], d[8];
#pragma unroll
        for (int c = 0; c < 8; ++c) { s[c] = a[c] + bb[c]; d[c] = a[c] - bb[c]; }
#pragma unroll
        for (int kk = 0; kk < 4; ++kk) {
#pragma unroll
            for (int c = 0; c < 8; ++c)
                t[2 * kk][c] = fmaf(C[2 * kk][r], s[c], t[2 * kk][c]);
#pragma unroll
            for (int c = 0; c < 8; ++c)
                t[2 * kk + 1][c] = fmaf(C[2 * kk + 1][r], d[c], t[2 * kk + 1][c]);
        }
    }

    // Quality factor scaling (uniform across warp: same b)
    float q = qf[b];
    float invF = (q < 50.0f) ? (q * 0.0002f) : (1.0f / (200.0f - 2.0f * q));

    float* op = out + (b << 20) + (hb << 7) + w;

    // Pass 2 (column symmetry) + quant scale + streaming stores.
#pragma unroll
    for (int k = 0; k < 8; ++k) {
        float u[4], v[4];
#pragma unroll
        for (int m = 0; m < 4; ++m) {
            u[m] = t[k][m] + t[k][7 - m];
            v[m] = t[k][m] - t[k][7 - m];
        }
#pragma unroll
        for (int l = 0; l < 8; ++l) {
            float o;
            if ((l & 1) == 0)
                o = fmaf(C[l][3], u[3], fmaf(C[l][2], u[2],
                        fmaf(C[l][1], u[1], C[l][0] * u[0])));
            else
                o = fmaf(C[l][3], v[3], fmaf(C[l][2], v[2],
                        fmaf(C[l][1], v[1], C[l][0] * v[0])));
            __stcs(&op[((k << 3) + l) << 14], (o * (100.0f / Qt[k][l])) * invF);
        }
    }
}

extern "C" void kernel_launch(void* const* d_in, const int* in_sizes, int n_in,
                              void* d_out, int out_size)
{
    const float* img = (const float*)d_in[0];
    const float* qf  = (const float*)d_in[1];
    if (n_in >= 2 && in_sizes[0] < in_sizes[1]) {
        img = (const float*)d_in[1];
        qf  = (const float*)d_in[0];
    }
    float* out = (float*)d_out;

    jpeg_dct_kernel<<<1024, 256>>>(img, qf, out);
}